// round 4
// baseline (speedup 1.0000x reference)
#include <cuda_runtime.h>
#include <cuda_bf16.h>
#include <cstdint>

#define BATCH     4096
#define FILTER    1024
#define RELC      19
#define RELD      1024
#define SLAB      (FILTER * RELC)      // 19456 floats per batch row
#define THREADS2  608                  // 19 * 32
#define KPT       32                   // f-chunks per thread (FILTER/32)

// Precomputed W[f][r] = sum_e U[f,e] * R[r,e], stored row-major [FILTER][RELC]
__device__ float W_global[SLAB];

// ---------------------------------------------------------------------------
// Kernel 1: W = U @ R^T.  One warp per f-row. float4 loads, shfl reduce.
// ---------------------------------------------------------------------------
__global__ void __launch_bounds__(256) compute_W_kernel(const float* __restrict__ U,
                                                        const float* __restrict__ R)
{
    int warp = threadIdx.x >> 5;
    int lane = threadIdx.x & 31;
    int f = blockIdx.x * 8 + warp;          // grid 128 * 8 warps = 1024 rows
    if (f >= FILTER) return;

    const float4* u4 = reinterpret_cast<const float4*>(U + (size_t)f * RELD);
    float4 u[8];
#pragma unroll
    for (int k = 0; k < 8; k++) u[k] = u4[lane + 32 * k];

#pragma unroll
    for (int r = 0; r < RELC; r++) {
        const float4* r4 = reinterpret_cast<const float4*>(R + (size_t)r * RELD);
        float acc = 0.f;
#pragma unroll
        for (int k = 0; k < 8; k++) {
            float4 rv = r4[lane + 32 * k];
            acc += u[k].x * rv.x + u[k].y * rv.y + u[k].z * rv.z + u[k].w * rv.w;
        }
#pragma unroll
        for (int o = 16; o > 0; o >>= 1)
            acc += __shfl_xor_sync(0xFFFFFFFFu, acc, o);
        if (lane == 0) W_global[f * RELC + r] = acc;
    }
}

// ---------------------------------------------------------------------------
// cp.async helpers
// ---------------------------------------------------------------------------
__device__ __forceinline__ void cp_async16(uint32_t smem_addr, const void* gmem) {
    asm volatile("cp.async.cg.shared.global [%0], [%1], 16;\n"
                 :: "r"(smem_addr), "l"(gmem) : "memory");
}
__device__ __forceinline__ void cp_commit() {
    asm volatile("cp.async.commit_group;\n" ::: "memory");
}
__device__ __forceinline__ void cp_wait1() {
    asm volatile("cp.async.wait_group 1;\n" ::: "memory");
}

// ---------------------------------------------------------------------------
// Kernel 2: scores[b,r] = sum_f conv[b,f,r] * W[f,r]
// Persistent blocks, double-buffered cp.async staging of the 76KB b-slab.
// Index identity: with tid = r + 19*g, slab element (tid + 608*k) has
//   f = g + 32*k,  r = tid % 19  ->  per-thread work is fully LINEAR.
// W is held in 32 registers per thread (loaded once per block).
// ---------------------------------------------------------------------------
__global__ void __launch_bounds__(THREADS2, 1)
score_kernel(const float* __restrict__ conv, float* __restrict__ out)
{
    extern __shared__ float smem[];
    float* buf[2] = { smem, smem + SLAB };         // 2 x 77824 B
    float* red    = smem + 2 * SLAB;               // 608 floats scratch

    const int tid = threadIdx.x;
    const int G   = gridDim.x;

    // Per-thread W slice in registers (block-lifetime, read once from gmem)
    float w[KPT];
#pragma unroll
    for (int k = 0; k < KPT; k++) w[k] = W_global[tid + THREADS2 * k];

    uint32_t sbase[2];
    sbase[0] = (uint32_t)__cvta_generic_to_shared(buf[0]);
    sbase[1] = (uint32_t)__cvta_generic_to_shared(buf[1]);

    // Prologue: prefetch first slab
    int b0 = blockIdx.x;
    {
        const char* src = reinterpret_cast<const char*>(conv + (size_t)b0 * SLAB);
#pragma unroll
        for (int j = 0; j < 8; j++) {
            int q = tid + THREADS2 * j;            // float4 index, 4864 total
            cp_async16(sbase[0] + (uint32_t)q * 16, src + (size_t)q * 16);
        }
    }
    cp_commit();

    int stage = 0;
    for (int b = b0; b < BATCH; b += G) {
        // Prefetch next slab into the other buffer
        int bn = b + G;
        if (bn < BATCH) {
            const char* src = reinterpret_cast<const char*>(conv + (size_t)bn * SLAB);
            uint32_t dst = sbase[stage ^ 1];
#pragma unroll
            for (int j = 0; j < 8; j++) {
                int q = tid + THREADS2 * j;
                cp_async16(dst + (uint32_t)q * 16, src + (size_t)q * 16);
            }
        }
        cp_commit();
        cp_wait1();            // current slab's group has landed
        __syncthreads();       // make all threads' copies visible; guards red[] reuse

        // Compute: linear smem reads, conflict-free
        const float* cb = buf[stage];
        float acc = 0.f;
#pragma unroll
        for (int k = 0; k < KPT; k++)
            acc = fmaf(cb[tid + THREADS2 * k], w[k], acc);

        // Reduce 32 partials (over g) per r
        red[tid] = acc;
        __syncthreads();
        if (tid < RELC) {
            float s = 0.f;
#pragma unroll
            for (int g = 0; g < 32; g++) s += red[tid + RELC * g];
            out[(size_t)b * RELC + tid] = s;
        }
        stage ^= 1;
    }
}

// ---------------------------------------------------------------------------
// Launch
// ---------------------------------------------------------------------------
extern "C" void kernel_launch(void* const* d_in, const int* in_sizes, int n_in,
                              void* d_out, int out_size)
{
    // Identify inputs by element count (robust to ordering)
    const float* conv = nullptr;   // 4096*1024*19 = 79691776
    const float* R    = nullptr;   // 19*1024      = 19456
    const float* U    = nullptr;   // 1024*1024    = 1048576
    for (int i = 0; i < n_in; i++) {
        switch (in_sizes[i]) {
            case 79691776: conv = (const float*)d_in[i]; break;
            case 19456:    R    = (const float*)d_in[i]; break;
            case 1048576:  U    = (const float*)d_in[i]; break;
        }
    }
    float* out = (float*)d_out;

    // Kernel 1: W = U @ R^T
    compute_W_kernel<<<128, 256>>>(U, R);

    // Kernel 2: persistent streamer
    int nsm = 148;
    cudaDeviceGetAttribute(&nsm, cudaDevAttrMultiProcessorCount, 0);
    size_t smem_bytes = (size_t)(2 * SLAB + THREADS2) * sizeof(float);   // 158080 B
    cudaFuncSetAttribute(score_kernel, cudaFuncAttributeMaxDynamicSharedMemorySize,
                         (int)smem_bytes);
    score_kernel<<<nsm, THREADS2, smem_bytes>>>(conv, out);
}